// round 13
// baseline (speedup 1.0000x reference)
#include <cuda_runtime.h>
#include <cuda_fp16.h>
#include <cstdint>

#define BATCH 64
#define SRC   512
#define HID   1024
#define HID2  2048
#define NEGV  -1e10f

// ------------------------------------------------------------------
// scratch (static device globals; no cudaMalloc allowed)
// ------------------------------------------------------------------
__device__ __align__(16) __half g_encH[SRC * BATCH * HID2];  // COMPACT row order
__device__ __align__(16) __half g_UH[HID * HID2];
__device__ float g_c[BATCH * HID];
__device__ float g_part[8 * BATCH * SRC];   // per-nc partial energies
__device__ int   g_rows[BATCH * SRC];       // global packed (b<<16|s) row list

struct MegaSync {
    int nrows;
    int k0done;
    int udone;
    int k1done;
    int tilerows[256];
};
__device__ MegaSync g_sync;

// ------------------------------------------------------------------
static __device__ __forceinline__ uint32_t smem_u32(const void* p) {
    uint32_t a;
    asm("{ .reg .u64 t; cvta.to.shared.u64 t, %1; cvt.u32.u64 %0, t; }" : "=r"(a) : "l"(p));
    return a;
}
static __device__ __forceinline__ int ld_acq(const int* p) {
    int v;
    asm volatile("ld.acquire.gpu.global.b32 %0, [%1];" : "=r"(v) : "l"(p) : "memory");
    return v;
}
#define SPIN_GE(ptr, val) do { while (ld_acq(ptr) < (val)) __nanosleep(64); } while (0)

static __device__ __forceinline__ void cp16(uint32_t dst, const void* src) {
    asm volatile("cp.async.cg.shared.global [%0], [%1], 16;" :: "r"(dst), "l"(src));
}
#define CP_COMMIT() asm volatile("cp.async.commit_group;" ::: "memory")
#define CP_WAIT(n)  asm volatile("cp.async.wait_group %0;" :: "n"(n) : "memory")

static __device__ __forceinline__ void ldm_x4(uint32_t* r, uint32_t addr) {
    asm volatile("ldmatrix.sync.aligned.m8n8.x4.shared.b16 {%0,%1,%2,%3}, [%4];"
                 : "=r"(r[0]), "=r"(r[1]), "=r"(r[2]), "=r"(r[3]) : "r"(addr));
}
static __device__ __forceinline__ void mma_f16(float* c, const uint32_t* a,
                                               uint32_t b0, uint32_t b1) {
    asm volatile(
        "mma.sync.aligned.m16n8k16.row.col.f32.f16.f16.f32 "
        "{%0,%1,%2,%3}, {%4,%5,%6,%7}, {%8,%9}, {%0,%1,%2,%3};"
        : "+f"(c[0]), "+f"(c[1]), "+f"(c[2]), "+f"(c[3])
        : "r"(a[0]), "r"(a[1]), "r"(a[2]), "r"(a[3]), "r"(b0), "r"(b1));
}

#define SWZ(o) ((uint32_t)(o) ^ ((((uint32_t)(o)) >> 3) & 0x70))

// SMEM layout (dynamic): stage = A(128x64 fp16, SW128) + B(128x64)
#define STAGE_BYTES 32768
#define OFF_SB      16384
#define OFF_VS      98304                // 128 floats
#define OFF_RED     98816                // 256 floats
#define OFF_ROWS    99840                // 128 ints
#define OFF_CTRL    100352               // 4 ints
#define SMEM_TOTAL  100480

// ------------------------------------------------------------------
// mega-kernel grid layout (dependencies point strictly BACKWARD)
// ------------------------------------------------------------------
#define NB_K0     64
#define NB_U      256
#define NB_K1     256
#define PROLOGUE  (NB_K0 + NB_U + NB_K1)       // 576
#define NTILES    256
#define GROUP_ENC 16
#define GROUP_K2  8
#define GROUP     (GROUP_ENC + GROUP_K2)       // 24
#define NB_TOTAL  (PROLOGUE + NTILES * GROUP)  // 6720

__global__ __launch_bounds__(256, 2) void mega(
    const float* __restrict__ enc, const float* __restrict__ U_w,
    const float* __restrict__ hidden, const float* __restrict__ W_w,
    const float* __restrict__ W_b, const float* __restrict__ U_b,
    const void* __restrict__ mask_raw, const float* __restrict__ v_w) {
    extern __shared__ __align__(128) char smem[];
    const int bx = blockIdx.x, t = threadIdx.x;

    // ============ phase K0: per-batch mask compaction ============
    if (bx < NB_K0) {
        int* sh_sidx = (int*)smem;            // 512
        int* sh_woff = sh_sidx + 512;         // 8
        int* sh_misc = sh_woff + 8;           // 3
        const int b = bx, lane = t & 31, wid = t >> 5;
        if (t == 0) { sh_misc[0] = 0; sh_misc[1] = 0; }
        __syncthreads();
        unsigned wtest = ((const unsigned*)mask_raw)[t];
        if (wtest > 1u) atomicOr(&sh_misc[0], 1);
        __syncthreads();
        const int mode = sh_misc[0];
        #pragma unroll
        for (int half = 0; half < 2; half++) {
            int s = half * 256 + t;
            int m = mode ? (int)((const unsigned char*)mask_raw)[b * SRC + s]
                         : ((const int*)mask_raw)[b * SRC + s];
            int keep = (m == 0);
            unsigned bal = __ballot_sync(0xffffffffu, keep);
            int pre = __popc(bal & ((1u << lane) - 1u));
            if (lane == 0) sh_woff[wid] = __popc(bal);
            __syncthreads();
            if (t == 0) {
                int acc = sh_misc[1];
                #pragma unroll
                for (int i = 0; i < 8; i++) { int v = sh_woff[i]; sh_woff[i] = acc; acc += v; }
                sh_misc[1] = acc;
            }
            __syncthreads();
            if (keep) sh_sidx[sh_woff[wid] + pre] = s;
            __syncthreads();
        }
        const int cnt = sh_misc[1];
        if (t == 0) sh_misc[2] = atomicAdd(&g_sync.nrows, cnt);
        __syncthreads();
        const int off = sh_misc[2];
        for (int j = t; j < cnt; j += 256)
            g_rows[off + j] = (b << 16) | sh_sidx[j];
        __syncthreads();
        if (t == 0) { __threadfence(); atomicAdd(&g_sync.k0done, 1); }
        return;
    }

    // ============ phase U: U_w fp32 -> fp16 ============
    if (bx < NB_K0 + NB_U) {
        size_t base = (size_t)(bx - NB_K0) * 256 + t;
        #pragma unroll
        for (int k = 0; k < 8; k++) {
            size_t i = base + (size_t)k * (NB_U * 256);
            float4 v = ((const float4*)U_w)[i];
            __half h[4] = {__float2half_rn(v.x), __float2half_rn(v.y),
                           __float2half_rn(v.z), __float2half_rn(v.w)};
            *(uint2*)(g_UH + 4 * i) = *(uint2*)h;
        }
        __syncthreads();
        if (t == 0) { __threadfence(); atomicAdd(&g_sync.udone, 1); }
        return;
    }

    // ============ phase K1: g_c = hidden.W^T + biases ============
    if (bx < PROLOGUE) {
        float* hs = (float*)smem;             // 32KB
        const int g = bx - (NB_K0 + NB_U);
        const int htile = g & 31, bg = g >> 5;
        const int w = t >> 5, lane = t & 31;
        #pragma unroll
        for (int i = 0; i < 8; i++) {
            int j = t + i * 256;
            ((float4*)hs)[j] = ((const float4*)hidden)[(size_t)bg * 2048 + j];
        }
        __syncthreads();
        #pragma unroll
        for (int r = 0; r < 4; r++) {
            const int h = htile * 32 + w * 4 + r;
            const float4* wr = (const float4*)(W_w + (size_t)h * HID);
            float acc[8] = {0.f, 0.f, 0.f, 0.f, 0.f, 0.f, 0.f, 0.f};
            #pragma unroll
            for (int i = 0; i < 8; i++) {
                float4 wv = wr[lane + i * 32];
                #pragma unroll
                for (int bb = 0; bb < 8; bb++) {
                    float4 hv = ((const float4*)(hs + bb * HID))[lane + i * 32];
                    acc[bb] += wv.x * hv.x + wv.y * hv.y + wv.z * hv.z + wv.w * hv.w;
                }
            }
            const float bias = W_b[h] + U_b[h];
            #pragma unroll
            for (int bb = 0; bb < 8; bb++) {
                float s = acc[bb];
                #pragma unroll
                for (int off = 16; off; off >>= 1) s += __shfl_xor_sync(0xffffffffu, s, off);
                if (lane == 0) g_c[(bg * 8 + bb) * HID + h] = s + bias;
            }
        }
        __syncthreads();
        if (t == 0) { __threadfence(); atomicAdd(&g_sync.k1done, 1); }
        return;
    }

    // ============ tile groups: [16 encC][8 k2] per tile ============
    const int gg = bx - PROLOGUE;
    const int tile = gg / GROUP, sub = gg % GROUP;

    if (sub < GROUP_ENC) {
        // ---- encC: convert 8 compact rows, gather via g_rows ----
        int* ctrl = (int*)smem;
        if (t == 0) { SPIN_GE(&g_sync.k0done, NB_K0); ctrl[0] = g_sync.nrows; }
        __syncthreads();
        const int nrows = ctrl[0];
        const int ci = tile * GROUP_ENC + sub;
        const int r0 = ci * 8;
        if (r0 >= nrows) return;
        const int valid = min(8, nrows - r0);
        const int w = t >> 5, lane = t & 31;
        if (w < valid) {
            int packed = g_rows[r0 + w];
            int s = packed & 0xffff, b = packed >> 16;
            const float4* src = (const float4*)(enc + (size_t)(s * BATCH + b) * HID2);
            uint2* dst = (uint2*)(g_encH + (size_t)(r0 + w) * HID2);
            float4 vv[16];
            #pragma unroll
            for (int i = 0; i < 16; i++) vv[i] = src[lane + 32 * i];
            #pragma unroll
            for (int i = 0; i < 16; i++) {
                __half h[4] = {__float2half_rn(vv[i].x), __float2half_rn(vv[i].y),
                               __float2half_rn(vv[i].z), __float2half_rn(vv[i].w)};
                dst[lane + 32 * i] = *(uint2*)h;
            }
        }
        __syncthreads();
        if (t == 0) { __threadfence(); atomicAdd(&g_sync.tilerows[tile], valid); }
        return;
    }

    // ---- k2: fp16 mma.sync fused energy on compact tile ----
    {
        const uint32_t sb = smem_u32(smem);
        const int nc = sub - GROUP_ENC;
        const int n0 = nc * 128;
        int* ctrl = (int*)(smem + OFF_CTRL);
        if (t == 0) {
            SPIN_GE(&g_sync.k0done, NB_K0);
            ctrl[0] = g_sync.nrows;
            SPIN_GE(&g_sync.udone, NB_U);
        }
        __syncthreads();
        const int nrows = ctrl[0];
        if (tile * 128 >= nrows) return;
        const int expected = min(128, nrows - tile * 128);
        if (t == 0) SPIN_GE(&g_sync.tilerows[tile], expected);
        __syncthreads();

        const int wid = t >> 5, lane = t & 31;
        const int wm = wid & 3, wn = wid >> 2;

        float* vs = (float*)(smem + OFF_VS);
        int* rows_sm = (int*)(smem + OFF_ROWS);
        if (t < 128) {
            vs[t] = v_w[n0 + t];
            int j = tile * 128 + t;
            rows_sm[t] = g_rows[j < nrows ? j : (nrows - 1)];
        }
        __syncthreads();

        uint32_t aBase[2], bBase[4];
        #pragma unroll
        for (int mt = 0; mt < 2; mt++)
            aBase[mt] = (uint32_t)((wm * 32 + mt * 16 + (lane & 15)) * 128 + (lane >> 4) * 16);
        #pragma unroll
        for (int gq = 0; gq < 4; gq++)
            bBase[gq] = (uint32_t)((wn * 64 + gq * 16 + (lane & 7) + ((lane >> 4) << 3)) * 128
                                   + ((lane >> 3) & 1) * 16);

        float c[2][8][4];
        #pragma unroll
        for (int mt = 0; mt < 2; mt++)
            #pragma unroll
            for (int nt = 0; nt < 8; nt++)
                #pragma unroll
                for (int e = 0; e < 4; e++) c[mt][nt][e] = 0.f;

        const __half* encBase = g_encH + (size_t)(tile * 128) * HID2;

        // staging helper (compact sequential A rows)
        #define DO_STAGE(KT) do {                                                   \
            const int _k0 = (KT) * 64;                                              \
            const uint32_t _sbase = sb + ((uint32_t)(KT) % 3u) * STAGE_BYTES;       \
            _Pragma("unroll")                                                       \
            for (int _i = 0; _i < 4; _i++) {                                        \
                int _idx = t + _i * 256;                                            \
                int _r = _idx >> 3, _kb = _idx & 7;                                 \
                uint32_t _so = SWZ(_r * 128 + _kb * 16);                            \
                cp16(_sbase + _so, encBase + (size_t)_r * HID2 + _k0 + _kb * 8);    \
                cp16(_sbase + OFF_SB + _so,                                         \
                     g_UH + (size_t)(n0 + _r) * HID2 + _k0 + _kb * 8);              \
            }                                                                       \
        } while (0)

        DO_STAGE(0);
        CP_COMMIT();
        DO_STAGE(1);
        CP_COMMIT();

        for (int g = 0; g < 32; g++) {
            CP_WAIT(1);
            __syncthreads();
            if (g < 30) DO_STAGE(g + 2);
            CP_COMMIT();

            const uint32_t sbase = sb + ((uint32_t)g % 3u) * STAGE_BYTES;
            #pragma unroll
            for (int ks = 0; ks < 4; ks++) {
                const uint32_t ko = (uint32_t)(ks * 32);
                uint32_t ah[2][4], bb[4][4];
                #pragma unroll
                for (int mt = 0; mt < 2; mt++) ldm_x4(ah[mt], sbase + SWZ(aBase[mt] + ko));
                #pragma unroll
                for (int gq = 0; gq < 4; gq++)
                    ldm_x4(bb[gq], sbase + OFF_SB + SWZ(bBase[gq] + ko));
                #pragma unroll
                for (int mt = 0; mt < 2; mt++)
                    #pragma unroll
                    for (int gq = 0; gq < 4; gq++) {
                        mma_f16(c[mt][2 * gq],     ah[mt], bb[gq][0], bb[gq][1]);
                        mma_f16(c[mt][2 * gq + 1], ah[mt], bb[gq][2], bb[gq][3]);
                    }
            }
        }
        #undef DO_STAGE

        // g_c needed only now — k1 long done by this point
        if (t == 0) SPIN_GE(&g_sync.k1done, NB_K1);
        __syncthreads();

        float esum[4] = {0.f, 0.f, 0.f, 0.f};
        #pragma unroll
        for (int mt = 0; mt < 2; mt++) {
            const int rA = wm * 32 + mt * 16 + (lane >> 2);
            const int bA = rows_sm[rA] >> 16, bB = rows_sm[rA + 8] >> 16;
            const float* cA = g_c + (size_t)bA * HID + n0;
            const float* cB = g_c + (size_t)bB * HID + n0;
            #pragma unroll
            for (int nt = 0; nt < 8; nt++) {
                const int hl = wn * 64 + nt * 8 + 2 * (lane & 3);
                float2 a2 = *(const float2*)(cA + hl);
                float2 b2 = *(const float2*)(cB + hl);
                float v0 = vs[hl], v1 = vs[hl + 1];
                float x0 = a2.x + c[mt][nt][0];
                float x1 = a2.y + c[mt][nt][1];
                float x2 = b2.x + c[mt][nt][2];
                float x3 = b2.y + c[mt][nt][3];
                float t0, t1, t2, t3;
                asm("tanh.approx.f32 %0, %1;" : "=f"(t0) : "f"(x0));
                asm("tanh.approx.f32 %0, %1;" : "=f"(t1) : "f"(x1));
                asm("tanh.approx.f32 %0, %1;" : "=f"(t2) : "f"(x2));
                asm("tanh.approx.f32 %0, %1;" : "=f"(t3) : "f"(x3));
                esum[0 + mt * 2] = fmaf(v0, t0, fmaf(v1, t1, esum[0 + mt * 2]));
                esum[1 + mt * 2] = fmaf(v0, t2, fmaf(v1, t3, esum[1 + mt * 2]));
            }
        }

        #pragma unroll
        for (int i = 0; i < 4; i++) {
            esum[i] += __shfl_xor_sync(0xffffffffu, esum[i], 1);
            esum[i] += __shfl_xor_sync(0xffffffffu, esum[i], 2);
        }
        float* red = (float*)(smem + OFF_RED);
        __syncthreads();
        if ((lane & 3) == 0) {
            #pragma unroll
            for (int i = 0; i < 4; i++) {
                int row = wm * 32 + (i >> 1) * 16 + (lane >> 2) + (i & 1) * 8;
                red[wn * 128 + row] = esum[i];
            }
        }
        __syncthreads();
        if (t < 128 && tile * 128 + t < nrows) {
            int packed = rows_sm[t];
            int s = packed & 0xffff, b = packed >> 16;
            g_part[(size_t)nc * (BATCH * SRC) + b * SRC + s] = red[t] + red[128 + t];
        }
    }
}

// ------------------------------------------------------------------
// K3: masked softmax over S per batch (sums the 8 nc partials)
// ------------------------------------------------------------------
__global__ void k3_softmax(const void* __restrict__ mask_raw, float* __restrict__ out) {
    const int b = blockIdx.x, t = threadIdx.x;
    const int lane = t & 31, wid = t >> 5;
    __shared__ int s_mode;
    __shared__ float sm[16];
    __shared__ float s_bcast;
    if (t == 0) s_mode = 0;
    __syncthreads();
    if (t < 256) {
        unsigned w = ((const unsigned*)mask_raw)[t];
        if (w > 1u) atomicOr(&s_mode, 1);
    }
    __syncthreads();
    int masked = s_mode ? (int)((const unsigned char*)mask_raw)[b * SRC + t]
                        : ((const int*)mask_raw)[b * SRC + t];
    float e;
    if (masked) {
        e = NEGV;
    } else {
        e = 0.f;
        #pragma unroll
        for (int nc = 0; nc < 8; nc++)
            e += g_part[(size_t)nc * (BATCH * SRC) + b * SRC + t];
    }

    float m = e;
    #pragma unroll
    for (int off = 16; off; off >>= 1) m = fmaxf(m, __shfl_xor_sync(0xffffffffu, m, off));
    if (lane == 0) sm[wid] = m;
    __syncthreads();
    if (wid == 0) {
        float v = (lane < 16) ? sm[lane] : -3.4e38f;
        #pragma unroll
        for (int off = 8; off; off >>= 1) v = fmaxf(v, __shfl_xor_sync(0xffffffffu, v, off));
        if (lane == 0) s_bcast = v;
    }
    __syncthreads();
    float p = __expf(e - s_bcast);
    float s = p;
    #pragma unroll
    for (int off = 16; off; off >>= 1) s += __shfl_xor_sync(0xffffffffu, s, off);
    __syncthreads();
    if (lane == 0) sm[wid] = s;
    __syncthreads();
    if (wid == 0) {
        float v = (lane < 16) ? sm[lane] : 0.f;
        #pragma unroll
        for (int off = 8; off; off >>= 1) v += __shfl_xor_sync(0xffffffffu, v, off);
        if (lane == 0) s_bcast = v;
    }
    __syncthreads();
    out[b * SRC + t] = p * __frcp_rn(s_bcast);
}

// ------------------------------------------------------------------
extern "C" void kernel_launch(void* const* d_in, const int* in_sizes, int n_in,
                              void* d_out, int out_size) {
    const float* hidden = (const float*)d_in[0];
    const float* enc    = (const float*)d_in[1];
    const void*  mask   = d_in[2];
    const float* W_w    = (const float*)d_in[3];
    const float* W_b    = (const float*)d_in[4];
    const float* U_w    = (const float*)d_in[5];
    const float* U_b    = (const float*)d_in[6];
    const float* v_w    = (const float*)d_in[7];
    float* out = (float*)d_out;

    static int init_done = 0;
    static void* sync_addr;
    if (!init_done) {
        cudaFuncSetAttribute(mega, cudaFuncAttributeMaxDynamicSharedMemorySize, SMEM_TOTAL);
        cudaGetSymbolAddress(&sync_addr, g_sync);
        init_done = 1;
    }

    cudaMemsetAsync(sync_addr, 0, sizeof(MegaSync), 0);
    mega<<<NB_TOTAL, 256, SMEM_TOTAL>>>(enc, U_w, hidden, W_w, W_b, U_b, mask, v_w);
    k3_softmax<<<BATCH, 512>>>(mask, out);
}